// round 1
// baseline (speedup 1.0000x reference)
#include <cuda_runtime.h>

// Bilinear flow warp:
//   img: [B=8, C=16, H=512, W=512] f32
//   flo: [B=8, 2,   H=512, W=512] f32  (ch0 = x disp, ch1 = y disp)
//   out: [B=8, C=16, H=512, W=512] f32
//
// One thread per (b,h,w) pixel; channel loop fully unrolled for MLP.

#define B_ 8
#define C_ 16
#define H_ 512
#define W_ 512
#define HW_ (H_ * W_)

__global__ __launch_bounds__(256) void warp_bilinear_kernel(
    const float* __restrict__ img,
    const float* __restrict__ flo,
    float* __restrict__ out)
{
    int idx = blockIdx.x * blockDim.x + threadIdx.x;  // over B*H*W = 2,097,152
    if (idx >= B_ * HW_) return;

    int w  = idx & (W_ - 1);
    int t  = idx >> 9;          // b*H + h
    int h  = t & (H_ - 1);
    int b  = t >> 9;

    // flo layout [B,2,H,W]
    int flo_base = ((b * 2) * H_ + h) * W_ + w;
    float fx = __ldg(flo + flo_base);
    float fy = __ldg(flo + flo_base + HW_);

    float px = (float)w + fx;
    float py = (float)h + fy;

    float x0f = floorf(px);
    float y0f = floorf(py);
    float xw  = px - x0f;       // weights from UNclamped floor (matches reference)
    float yw  = py - y0f;

    int x0 = (int)fminf(fmaxf(x0f,        0.0f), (float)(W_ - 1));
    int x1 = (int)fminf(fmaxf(x0f + 1.0f, 0.0f), (float)(W_ - 1));
    int y0 = (int)fminf(fmaxf(y0f,        0.0f), (float)(H_ - 1));
    int y1 = (int)fminf(fmaxf(y0f + 1.0f, 0.0f), (float)(H_ - 1));

    float wa = (1.0f - xw) * (1.0f - yw);
    float wb = (1.0f - xw) * yw;
    float wc = xw * (1.0f - yw);
    float wd = xw * yw;

    int o00 = y0 * W_ + x0;
    int o10 = y1 * W_ + x0;
    int o01 = y0 * W_ + x1;
    int o11 = y1 * W_ + x1;

    const float* ibase = img + (size_t)b * C_ * HW_;
    float*       obase = out + (size_t)b * C_ * HW_ + h * W_ + w;

    #pragma unroll
    for (int c = 0; c < C_; c++) {
        const float* p = ibase + c * HW_;
        float Ia = __ldg(p + o00);
        float Ib = __ldg(p + o10);
        float Ic = __ldg(p + o01);
        float Id = __ldg(p + o11);
        obase[c * HW_] = wa * Ia + wb * Ib + wc * Ic + wd * Id;
    }
}

extern "C" void kernel_launch(void* const* d_in, const int* in_sizes, int n_in,
                              void* d_out, int out_size)
{
    const float* img = (const float*)d_in[0];
    const float* flo = (const float*)d_in[1];
    float* out = (float*)d_out;

    const int total = B_ * HW_;           // 2,097,152 pixels
    const int threads = 256;
    const int blocks = (total + threads - 1) / threads;  // 8192
    warp_bilinear_kernel<<<blocks, threads>>>(img, flo, out);
}